// round 3
// baseline (speedup 1.0000x reference)
#include <cuda_runtime.h>
#include <math.h>

#define Bc 8
#define Nn 1024
#define Dm 1024
#define Hh 16
#define HD 64
#define Tt_ 8192
#define NE 4
#define MH 2048

// ---------------- scratch (static device allocations only) ----------------
// layout (float offsets, MM = 8M floats):
// 0:xt 1:trt 2:S 3:Sn 4:q 5:k 6:v 7:y 8:xs 9:xf 10..11:h 12:tt 13:gw+gatesum
__device__ __align__(16) float g_scratch[(size_t)14 * 8 * 1024 * 1024];
__device__ int g_iscratch[64 + NE * Tt_];

// ---------------- transpose: in [B][R=1024][C=1024] -> out [B][C][R] --------
__global__ void k_transpose(const float* __restrict__ in, float* __restrict__ out) {
    __shared__ float tile[32][33];
    int b = blockIdx.z;
    int c0 = blockIdx.x * 32, r0 = blockIdx.y * 32;
    const float* ip = in + (size_t)b * Nn * Dm;
    float* op = out + (size_t)b * Nn * Dm;
    int tx = threadIdx.x, ty = threadIdx.y;
#pragma unroll
    for (int i = 0; i < 32; i += 8)
        tile[ty + i][tx] = ip[(size_t)(r0 + ty + i) * Dm + c0 + tx];
    __syncthreads();
#pragma unroll
    for (int i = 0; i < 32; i += 8)
        op[(size_t)(c0 + ty + i) * Nn + r0 + tx] = tile[tx][ty + i];
}

// ---------------- decomposition: 3 depthwise reflect convs, softmax-mixed ---
__global__ void k_decomp(const float* __restrict__ xt, const float* __restrict__ dw7,
                         const float* __restrict__ dw25, const float* __restrict__ dw49,
                         const float* __restrict__ alpha, float* __restrict__ trt) {
    int d = blockIdx.x, b = blockIdx.y;
    __shared__ float row[Nn];
    __shared__ float kw[96];
    int tid = threadIdx.x;
    const float* xr = xt + ((size_t)b * Dm + d) * Nn;
    for (int i = tid; i < Nn; i += blockDim.x) row[i] = xr[i];
    if (tid < 7) kw[tid] = dw7[d * 7 + tid];
    if (tid < 25) kw[7 + tid] = dw25[d * 25 + tid];
    if (tid < 49) kw[32 + tid] = dw49[d * 49 + tid];
    __syncthreads();
    float a0 = alpha[0], a1 = alpha[1], a2 = alpha[2];
    float mx = fmaxf(a0, fmaxf(a1, a2));
    float e0 = expf(a0 - mx), e1 = expf(a1 - mx), e2 = expf(a2 - mx);
    float inv = 1.f / (e0 + e1 + e2);
    float w0 = e0 * inv, w1 = e1 * inv, w2 = e2 * inv;
    float* out = trt + ((size_t)b * Dm + d) * Nn;
    for (int n = tid; n < Nn; n += blockDim.x) {
        float acc = 0.f;
#pragma unroll
        for (int j = 0; j < 7; j++) {
            int t = n - 3 + j; t = t < 0 ? -t : (t >= Nn ? 2 * (Nn - 1) - t : t);
            acc += w0 * kw[j] * row[t];
        }
#pragma unroll
        for (int j = 0; j < 25; j++) {
            int t = n - 12 + j; t = t < 0 ? -t : (t >= Nn ? 2 * (Nn - 1) - t : t);
            acc += w1 * kw[7 + j] * row[t];
        }
#pragma unroll
        for (int j = 0; j < 49; j++) {
            int t = n - 24 + j; t = t < 0 ? -t : (t >= Nn ? 2 * (Nn - 1) - t : t);
            acc += w2 * kw[32 + j] * row[t];
        }
        out[n] = acc;
    }
}

// ---------------- S[b,n,d] = x[b,n,d] - Trt[b,d,n] (tiled transpose-sub) ----
__global__ void k_makeS(const float* __restrict__ x, const float* __restrict__ trt,
                        float* __restrict__ S) {
    __shared__ float tile[32][33];
    int b = blockIdx.z;
    int d0 = blockIdx.x * 32, n0 = blockIdx.y * 32;
    int tx = threadIdx.x, ty = threadIdx.y;
#pragma unroll
    for (int i = 0; i < 32; i += 8)
        tile[ty + i][tx] = trt[(size_t)b * Dm * Nn + (size_t)(d0 + ty + i) * Nn + n0 + tx];
    __syncthreads();
#pragma unroll
    for (int i = 0; i < 32; i += 8) {
        size_t idx = (size_t)b * Nn * Dm + (size_t)(n0 + ty + i) * Dm + d0 + tx;
        S[idx] = x[idx] - tile[tx][ty + i];
    }
}

// ---------------- out[b,n,d] = xs[b,n,d] + Tt[b,d,n] ------------------------
__global__ void k_final(const float* __restrict__ xs, const float* __restrict__ tt,
                        float* __restrict__ out) {
    __shared__ float tile[32][33];
    int b = blockIdx.z;
    int d0 = blockIdx.x * 32, n0 = blockIdx.y * 32;
    int tx = threadIdx.x, ty = threadIdx.y;
#pragma unroll
    for (int i = 0; i < 32; i += 8)
        tile[ty + i][tx] = tt[(size_t)b * Dm * Nn + (size_t)(d0 + ty + i) * Nn + n0 + tx];
    __syncthreads();
#pragma unroll
    for (int i = 0; i < 32; i += 8) {
        size_t idx = (size_t)b * Nn * Dm + (size_t)(n0 + ty + i) * Dm + d0 + tx;
        out[idx] = xs[idx] + tile[tx][ty + i];
    }
}

// ---------------- layernorm over last dim (1024) ---------------------------
__global__ void k_ln(const float* __restrict__ x, const float* __restrict__ g,
                     const float* __restrict__ bta, float* __restrict__ out) {
    int row = blockIdx.x;
    int tid = threadIdx.x;
    const float* xr = x + (size_t)row * Dm;
    __shared__ float red[256];
    float s = 0.f;
    for (int i = tid; i < Dm; i += 256) s += xr[i];
    red[tid] = s; __syncthreads();
    for (int st = 128; st > 0; st >>= 1) { if (tid < st) red[tid] += red[tid + st]; __syncthreads(); }
    float mean = red[0] / Dm;
    __syncthreads();
    float v = 0.f;
    for (int i = tid; i < Dm; i += 256) { float dd = xr[i] - mean; v += dd * dd; }
    red[tid] = v; __syncthreads();
    for (int st = 128; st > 0; st >>= 1) { if (tid < st) red[tid] += red[tid + st]; __syncthreads(); }
    float inv = rsqrtf(red[0] / Dm + 1e-5f);
    for (int i = tid; i < Dm; i += 256)
        out[(size_t)row * Dm + i] = (xr[i] - mean) * inv * g[i] + bta[i];
}

// ---------------- generic NT SGEMM: C = A[M,K] * Bm[N,K]^T + bias ----------
// gidx && !gscale : A rows gathered via gidx (MoE up-proj)
// gscale          : C rows scattered via gidx, C[gidx[m]] += (acc+bias)*gscale[m]
// res             : C = acc + bias + res (fused residual)
// gelu_flag       : exact-erf GELU epilogue
__global__ void __launch_bounds__(256) k_sgemm(
    const float* __restrict__ A, const float* __restrict__ Bm,
    const float* __restrict__ bias, const float* __restrict__ res,
    float* __restrict__ C, int M, const int* __restrict__ Mdev,
    int Npar, int K, const int* __restrict__ gidx,
    const float* __restrict__ gscale, int gelu_flag) {
    if (Mdev) M = *Mdev;
    int bm = blockIdx.y * 128, bn = blockIdx.x * 128;
    if (bm >= M) return;
    __shared__ float As[8][128];
    __shared__ float Bs[8][128];
    int tid = threadIdx.x;
    int lr = tid >> 1, lc = (tid & 1) * 4;
    int am = bm + lr;
    bool av = am < M;
    int asrc = 0;
    if (av) asrc = (gidx && !gscale) ? gidx[am] : am;
    const float* Ap = A + (size_t)asrc * K + lc;
    const float* Bp = Bm + (size_t)(bn + lr) * K + lc;
    float acc[8][8];
#pragma unroll
    for (int i = 0; i < 8; i++)
#pragma unroll
        for (int j = 0; j < 8; j++) acc[i][j] = 0.f;
    int tx = tid & 15, ty = tid >> 4;
    for (int k0 = 0; k0 < K; k0 += 8) {
        float4 a4 = av ? *(const float4*)(Ap + k0) : make_float4(0.f, 0.f, 0.f, 0.f);
        float4 b4 = *(const float4*)(Bp + k0);
        As[lc + 0][lr] = a4.x; As[lc + 1][lr] = a4.y;
        As[lc + 2][lr] = a4.z; As[lc + 3][lr] = a4.w;
        Bs[lc + 0][lr] = b4.x; Bs[lc + 1][lr] = b4.y;
        Bs[lc + 2][lr] = b4.z; Bs[lc + 3][lr] = b4.w;
        __syncthreads();
#pragma unroll
        for (int kk = 0; kk < 8; kk++) {
            float ar[8], br[8];
#pragma unroll
            for (int i = 0; i < 8; i++) ar[i] = As[kk][ty * 8 + i];
#pragma unroll
            for (int j = 0; j < 8; j++) br[j] = Bs[kk][tx * 8 + j];
#pragma unroll
            for (int i = 0; i < 8; i++)
#pragma unroll
                for (int j = 0; j < 8; j++) acc[i][j] += ar[i] * br[j];
        }
        __syncthreads();
    }
#pragma unroll
    for (int i = 0; i < 8; i++) {
        int m = bm + ty * 8 + i;
        if (m >= M) continue;
        int cr = gscale ? gidx[m] : m;
        float sc = gscale ? gscale[m] : 1.f;
        float* Crow = C + (size_t)cr * Npar;
        const float* Rrow = res ? res + (size_t)m * Npar : nullptr;
#pragma unroll
        for (int j = 0; j < 8; j++) {
            int n = bn + tx * 8 + j;
            float vv = acc[i][j] + (bias ? bias[n] : 0.f);
            if (gelu_flag) vv = 0.5f * vv * (1.f + erff(vv * 0.70710678118654752f));
            if (gscale) Crow[n] += vv * sc;
            else Crow[n] = vv + (Rrow ? Rrow[n] : 0.f);
        }
    }
}

// ---------------- flash-style ALiBi attention ------------------------------
__global__ void __launch_bounds__(64) k_attn(const float* __restrict__ q,
                                             const float* __restrict__ k,
                                             const float* __restrict__ v,
                                             float* __restrict__ y) {
    int qt = blockIdx.x, h = blockIdx.y, b = blockIdx.z;
    int t = threadIdx.x;
    int qi = qt * 64 + t;
    __shared__ float Ks[64][64];
    __shared__ float Vs[64][64];
    float qr[64];
    const float* qp = q + ((size_t)(b * Nn + qi) * Dm + h * HD);
#pragma unroll
    for (int c = 0; c < 64; c += 4) {
        float4 f = *(const float4*)(qp + c);
        qr[c] = f.x; qr[c + 1] = f.y; qr[c + 2] = f.z; qr[c + 3] = f.w;
    }
    float o[64];
#pragma unroll
    for (int c = 0; c < 64; c++) o[c] = 0.f;
    float m = -1e30f, l = 0.f;
    float slope = exp2f(-0.5f * (float)(h + 1));
    for (int c0 = 0; c0 < Nn; c0 += 64) {
        for (int rr = 0; rr < 64; rr++) {
            size_t base = ((size_t)(b * Nn + c0 + rr) * Dm + h * HD);
            Ks[rr][t] = k[base + t];
            Vs[rr][t] = v[base + t];
        }
        __syncthreads();
        for (int j = 0; j < 64; j++) {
            float s0 = 0.f, s1 = 0.f, s2 = 0.f, s3 = 0.f;
#pragma unroll
            for (int c = 0; c < 64; c += 4) {
                s0 += qr[c] * Ks[j][c];
                s1 += qr[c + 1] * Ks[j][c + 1];
                s2 += qr[c + 2] * Ks[j][c + 2];
                s3 += qr[c + 3] * Ks[j][c + 3];
            }
            float s = (s0 + s1 + s2 + s3) * 0.125f;
            int dj = (c0 + j) - qi;
            if (dj > 0) s -= slope * (float)dj;
            float mn = fmaxf(m, s);
            float p = expf(s - mn);
            if (mn > m) {
                float corr = expf(m - mn);
                l *= corr;
#pragma unroll
                for (int c = 0; c < 64; c++) o[c] *= corr;
            }
            m = mn;
            l += p;
#pragma unroll
            for (int c = 0; c < 64; c++) o[c] += p * Vs[j][c];
        }
        __syncthreads();
    }
    float invl = 1.f / l;
    float* yp = y + ((size_t)(b * Nn + qi) * Dm + h * HD);
#pragma unroll
    for (int c = 0; c < 64; c++) yp[c] = o[c] * invl;
}

// ---------------- router: softmax gates, top-2, expert lists, aux sums -----
__global__ void k_router(const float* __restrict__ xf, const float* __restrict__ rw,
                         float* __restrict__ gatesum, int* __restrict__ icnt,
                         int* __restrict__ idxbuf, float* __restrict__ gwbuf) {
    int t = blockIdx.x;
    int tid = threadIdx.x;  // 128
    const float* xr = xf + (size_t)t * Dm;
    float a0 = 0.f, a1 = 0.f, a2 = 0.f, a3 = 0.f;
    for (int i = tid; i < Dm; i += 128) {
        float xv = xr[i];
        a0 += xv * rw[i];
        a1 += xv * rw[Dm + i];
        a2 += xv * rw[2 * Dm + i];
        a3 += xv * rw[3 * Dm + i];
    }
    __shared__ float red[4][128];
    red[0][tid] = a0; red[1][tid] = a1; red[2][tid] = a2; red[3][tid] = a3;
    __syncthreads();
    for (int st = 64; st > 0; st >>= 1) {
        if (tid < st) {
            red[0][tid] += red[0][tid + st];
            red[1][tid] += red[1][tid + st];
            red[2][tid] += red[2][tid + st];
            red[3][tid] += red[3][tid + st];
        }
        __syncthreads();
    }
    if (tid == 0) {
        float g[4];
        float mx = -1e30f;
        for (int e = 0; e < 4; e++) { g[e] = red[e][0]; mx = fmaxf(mx, g[e]); }
        float ssum = 0.f;
        for (int e = 0; e < 4; e++) { g[e] = expf(g[e] - mx); ssum += g[e]; }
        float sinv = 1.f / ssum;
        for (int e = 0; e < 4; e++) g[e] *= sinv;
        int i1 = 0;
        for (int e = 1; e < 4; e++) if (g[e] > g[i1]) i1 = e;
        int i2 = -1;
        for (int e = 0; e < 4; e++) if (e != i1 && (i2 < 0 || g[e] > g[i2])) i2 = e;
        float sum2 = g[i1] + g[i2];
        if (sum2 < 1e-9f) sum2 = 1e-9f;
        float w1 = g[i1] / sum2, w2 = g[i2] / sum2;
        for (int e = 0; e < 4; e++) atomicAdd(&gatesum[e], g[e]);
        int p1 = atomicAdd(&icnt[i1], 1);
        idxbuf[i1 * Tt_ + p1] = t; gwbuf[i1 * Tt_ + p1] = w1;
        int p2 = atomicAdd(&icnt[i2], 1);
        idxbuf[i2 * Tt_ + p2] = t; gwbuf[i2 * Tt_ + p2] = w2;
    }
}

__global__ void k_aux(const float* __restrict__ gatesum, const int* __restrict__ icnt,
                      float* __restrict__ out, int out_size) {
    const int MAIN = Bc * Nn * Dm;
    if (out_size <= MAIN) return;
    float aux = 0.f;
    for (int e = 0; e < 4; e++)
        aux += (gatesum[e] / (float)Tt_) * ((float)icnt[e] / (float)Tt_);
    out[out_size - 1] = 4.f * aux;
}

__global__ void k_zero(int* __restrict__ icnt, float* __restrict__ gatesum) {
    int i = threadIdx.x;
    if (i < 8) icnt[i] = 0;
    if (i < 4) gatesum[i] = 0.f;
}

// ---------------- trend conv: k=5, zero pad 2, + bias ----------------------
__global__ void k_trend(const float* __restrict__ trt, const float* __restrict__ tw,
                        const float* __restrict__ tb, float* __restrict__ tt) {
    int d = blockIdx.x, b = blockIdx.y;
    int tid = threadIdx.x;
    __shared__ float row[Nn];
    const float* rp = trt + ((size_t)b * Dm + d) * Nn;
    for (int i = tid; i < Nn; i += blockDim.x) row[i] = rp[i];
    __syncthreads();
    float w[5];
#pragma unroll
    for (int j = 0; j < 5; j++) w[j] = tw[d * 5 + j];
    float bb = tb[d];
    float* op = tt + ((size_t)b * Dm + d) * Nn;
    for (int n = tid; n < Nn; n += blockDim.x) {
        float acc = bb;
#pragma unroll
        for (int j = 0; j < 5; j++) {
            int t = n - 2 + j;
            if (t >= 0 && t < Nn) acc += w[j] * row[t];
        }
        op[n] = acc;
    }
}

// ---------------- launch ---------------------------------------------------
extern "C" void kernel_launch(void* const* d_in, const int* in_sizes, int n_in,
                              void* d_out, int out_size) {
    const float* x = (const float*)d_in[0];
    const float* qw = (const float*)d_in[1];  const float* qb = (const float*)d_in[2];
    const float* kw_ = (const float*)d_in[3]; const float* kb = (const float*)d_in[4];
    const float* vw = (const float*)d_in[5];  const float* vb = (const float*)d_in[6];
    const float* ow = (const float*)d_in[7];  const float* ob = (const float*)d_in[8];
    const float* n1g = (const float*)d_in[9]; const float* n1b = (const float*)d_in[10];
    const float* n2g = (const float*)d_in[11]; const float* n2b = (const float*)d_in[12];
    const float* alpha = (const float*)d_in[13];
    const float* dw7 = (const float*)d_in[14];
    const float* dw25 = (const float*)d_in[15];
    const float* dw49 = (const float*)d_in[16];
    const float* router_w = (const float*)d_in[17];
    const float* ew1 = (const float*)d_in[18]; const float* eb1 = (const float*)d_in[19];
    const float* ew2 = (const float*)d_in[20]; const float* eb2 = (const float*)d_in[21];
    const float* tw = (const float*)d_in[22];  const float* tb = (const float*)d_in[23];
    float* out = (float*)d_out;

    float* sc; cudaGetSymbolAddress((void**)&sc, g_scratch);
    int* isc; cudaGetSymbolAddress((void**)&isc, g_iscratch);
    const size_t MM = (size_t)8 * 1024 * 1024;
    float* xt = sc;            float* trt = sc + MM;
    float* S  = sc + 2 * MM;   float* Sn  = sc + 3 * MM;
    float* q  = sc + 4 * MM;   float* kk  = sc + 5 * MM;
    float* vv = sc + 6 * MM;   float* y   = sc + 7 * MM;
    float* xs = sc + 8 * MM;   float* xf  = sc + 9 * MM;
    float* hbuf = sc + 10 * MM;
    float* tt = sc + 12 * MM;
    float* gwbuf = sc + 13 * MM;
    float* gatesum = sc + 13 * MM + 4 * Tt_;
    int* icnt = isc;
    int* idxbuf = isc + 64;

    dim3 tb32(32, 8);
    k_zero<<<1, 32>>>(icnt, gatesum);
    k_transpose<<<dim3(32, 32, Bc), tb32>>>(x, xt);
    k_decomp<<<dim3(Dm, Bc), 128>>>(xt, dw7, dw25, dw49, alpha, trt);
    k_makeS<<<dim3(32, 32, Bc), tb32>>>(x, trt, S);
    k_ln<<<Tt_, 256>>>(S, n1g, n1b, Sn);
    dim3 gqkv(Dm / 128, Tt_ / 128);
    k_sgemm<<<gqkv, 256>>>(Sn, qw, qb, nullptr, q, Tt_, nullptr, Dm, Dm, nullptr, nullptr, 0);
    k_sgemm<<<gqkv, 256>>>(Sn, kw_, kb, nullptr, kk, Tt_, nullptr, Dm, Dm, nullptr, nullptr, 0);
    k_sgemm<<<gqkv, 256>>>(Sn, vw, vb, nullptr, vv, Tt_, nullptr, Dm, Dm, nullptr, nullptr, 0);
    k_attn<<<dim3(Nn / 64, Hh, Bc), 64>>>(q, kk, vv, y);
    k_sgemm<<<gqkv, 256>>>(y, ow, ob, S, xs, Tt_, nullptr, Dm, Dm, nullptr, nullptr, 0);
    k_ln<<<Tt_, 256>>>(xs, n2g, n2b, xf);
    k_router<<<Tt_, 128>>>(xf, router_w, gatesum, icnt, idxbuf, gwbuf);
    k_aux<<<1, 1>>>(gatesum, icnt, out, out_size);
    for (int e = 0; e < NE; e++) {
        k_sgemm<<<dim3(MH / 128, Tt_ / 128), 256>>>(
            xf, ew1 + (size_t)e * MH * Dm, eb1 + e * MH, nullptr, hbuf,
            0, &icnt[e], MH, Dm, idxbuf + e * Tt_, nullptr, 1);
        k_sgemm<<<dim3(Dm / 128, Tt_ / 128), 256>>>(
            hbuf, ew2 + (size_t)e * Dm * MH, eb2 + e * Dm, nullptr, xs,
            0, &icnt[e], Dm, MH, idxbuf + e * Tt_, gwbuf + e * Tt_, 0);
    }
    k_trend<<<dim3(Dm, Bc), 128>>>(trt, tw, tb, tt);
    k_final<<<dim3(32, 32, Bc), tb32>>>(xs, tt, out);
}

// round 5
// speedup vs baseline: 2.5420x; 2.5420x over previous
#include <cuda_runtime.h>
#include <math.h>
#include <stdint.h>

#define Bc 8
#define Nn 1024
#define Dm 1024
#define Hh 16
#define HD 64
#define Tt_ 8192
#define NE 4
#define MH 2048

// ---------------- scratch (static device allocations only) ----------------
__device__ __align__(16) float g_scratch[(size_t)14 * 8 * 1024 * 1024];
__device__ int g_iscratch[64 + NE * Tt_];

// ---------------- transpose: in [B][R=1024][C=1024] -> out [B][C][R] --------
__global__ void k_transpose(const float* __restrict__ in, float* __restrict__ out) {
    __shared__ float tile[32][33];
    int b = blockIdx.z;
    int c0 = blockIdx.x * 32, r0 = blockIdx.y * 32;
    const float* ip = in + (size_t)b * Nn * Dm;
    float* op = out + (size_t)b * Nn * Dm;
    int tx = threadIdx.x, ty = threadIdx.y;
#pragma unroll
    for (int i = 0; i < 32; i += 8)
        tile[ty + i][tx] = ip[(size_t)(r0 + ty + i) * Dm + c0 + tx];
    __syncthreads();
#pragma unroll
    for (int i = 0; i < 32; i += 8)
        op[(size_t)(c0 + ty + i) * Nn + r0 + tx] = tile[tx][ty + i];
}

// ---------------- decomposition: 3 depthwise reflect convs, softmax-mixed ---
__global__ void k_decomp(const float* __restrict__ xt, const float* __restrict__ dw7,
                         const float* __restrict__ dw25, const float* __restrict__ dw49,
                         const float* __restrict__ alpha, float* __restrict__ trt) {
    int d = blockIdx.x, b = blockIdx.y;
    __shared__ float row[Nn];
    __shared__ float kw[96];
    int tid = threadIdx.x;
    const float* xr = xt + ((size_t)b * Dm + d) * Nn;
    for (int i = tid; i < Nn; i += blockDim.x) row[i] = xr[i];
    if (tid < 7) kw[tid] = dw7[d * 7 + tid];
    if (tid < 25) kw[7 + tid] = dw25[d * 25 + tid];
    if (tid < 49) kw[32 + tid] = dw49[d * 49 + tid];
    __syncthreads();
    float a0 = alpha[0], a1 = alpha[1], a2 = alpha[2];
    float mx = fmaxf(a0, fmaxf(a1, a2));
    float e0 = expf(a0 - mx), e1 = expf(a1 - mx), e2 = expf(a2 - mx);
    float inv = 1.f / (e0 + e1 + e2);
    float w0 = e0 * inv, w1 = e1 * inv, w2 = e2 * inv;
    float* out = trt + ((size_t)b * Dm + d) * Nn;
    for (int n = tid; n < Nn; n += blockDim.x) {
        float acc = 0.f;
#pragma unroll
        for (int j = 0; j < 7; j++) {
            int t = n - 3 + j; t = t < 0 ? -t : (t >= Nn ? 2 * (Nn - 1) - t : t);
            acc += w0 * kw[j] * row[t];
        }
#pragma unroll
        for (int j = 0; j < 25; j++) {
            int t = n - 12 + j; t = t < 0 ? -t : (t >= Nn ? 2 * (Nn - 1) - t : t);
            acc += w1 * kw[7 + j] * row[t];
        }
#pragma unroll
        for (int j = 0; j < 49; j++) {
            int t = n - 24 + j; t = t < 0 ? -t : (t >= Nn ? 2 * (Nn - 1) - t : t);
            acc += w2 * kw[32 + j] * row[t];
        }
        out[n] = acc;
    }
}

// ---------------- S[b,n,d] = x[b,n,d] - Trt[b,d,n] (tiled transpose-sub) ----
__global__ void k_makeS(const float* __restrict__ x, const float* __restrict__ trt,
                        float* __restrict__ S) {
    __shared__ float tile[32][33];
    int b = blockIdx.z;
    int d0 = blockIdx.x * 32, n0 = blockIdx.y * 32;
    int tx = threadIdx.x, ty = threadIdx.y;
#pragma unroll
    for (int i = 0; i < 32; i += 8)
        tile[ty + i][tx] = trt[(size_t)b * Dm * Nn + (size_t)(d0 + ty + i) * Nn + n0 + tx];
    __syncthreads();
#pragma unroll
    for (int i = 0; i < 32; i += 8) {
        size_t idx = (size_t)b * Nn * Dm + (size_t)(n0 + ty + i) * Dm + d0 + tx;
        S[idx] = x[idx] - tile[tx][ty + i];
    }
}

// ---------------- out[b,n,d] = xs[b,n,d] + Tt[b,d,n] ------------------------
__global__ void k_final(const float* __restrict__ xs, const float* __restrict__ tt,
                        float* __restrict__ out) {
    __shared__ float tile[32][33];
    int b = blockIdx.z;
    int d0 = blockIdx.x * 32, n0 = blockIdx.y * 32;
    int tx = threadIdx.x, ty = threadIdx.y;
#pragma unroll
    for (int i = 0; i < 32; i += 8)
        tile[ty + i][tx] = tt[(size_t)b * Dm * Nn + (size_t)(d0 + ty + i) * Nn + n0 + tx];
    __syncthreads();
#pragma unroll
    for (int i = 0; i < 32; i += 8) {
        size_t idx = (size_t)b * Nn * Dm + (size_t)(n0 + ty + i) * Dm + d0 + tx;
        out[idx] = xs[idx] + tile[tx][ty + i];
    }
}

// ---------------- layernorm over last dim (1024) ---------------------------
__global__ void k_ln(const float* __restrict__ x, const float* __restrict__ g,
                     const float* __restrict__ bta, float* __restrict__ out) {
    int row = blockIdx.x;
    int tid = threadIdx.x;
    const float* xr = x + (size_t)row * Dm;
    __shared__ float red[256];
    float s = 0.f;
    for (int i = tid; i < Dm; i += 256) s += xr[i];
    red[tid] = s; __syncthreads();
    for (int st = 128; st > 0; st >>= 1) { if (tid < st) red[tid] += red[tid + st]; __syncthreads(); }
    float mean = red[0] / Dm;
    __syncthreads();
    float v = 0.f;
    for (int i = tid; i < Dm; i += 256) { float dd = xr[i] - mean; v += dd * dd; }
    red[tid] = v; __syncthreads();
    for (int st = 128; st > 0; st >>= 1) { if (tid < st) red[tid] += red[tid + st]; __syncthreads(); }
    float inv = rsqrtf(red[0] / Dm + 1e-5f);
    for (int i = tid; i < Dm; i += 256)
        out[(size_t)row * Dm + i] = (xr[i] - mean) * inv * g[i] + bta[i];
}

// ---------------- TF32 tensor-core NT GEMM: C = A[M,K]*Bm[N,K]^T + bias -----
// Same contract as old k_sgemm:
//   gidx && !gscale : A rows gathered via gidx
//   gscale          : C rows scattered, C[gidx[m]] += (acc+bias[+gelu])*gscale[m]
//   res             : C = acc + bias + res
//   gelu_flag       : exact erf GELU epilogue
__device__ __forceinline__ float4 cvt4_tf32(float4 v) {
    uint32_t a, b, c, d;
    asm("cvt.rna.tf32.f32 %0,%1;" : "=r"(a) : "f"(v.x));
    asm("cvt.rna.tf32.f32 %0,%1;" : "=r"(b) : "f"(v.y));
    asm("cvt.rna.tf32.f32 %0,%1;" : "=r"(c) : "f"(v.z));
    asm("cvt.rna.tf32.f32 %0,%1;" : "=r"(d) : "f"(v.w));
    float4 r;
    r.x = __uint_as_float(a); r.y = __uint_as_float(b);
    r.z = __uint_as_float(c); r.w = __uint_as_float(d);
    return r;
}

__device__ __forceinline__ void mma_tf32(float c[4], const uint32_t a[4], const uint32_t b[2]) {
    asm volatile(
        "mma.sync.aligned.m16n8k8.row.col.f32.tf32.tf32.f32 "
        "{%0,%1,%2,%3},{%4,%5,%6,%7},{%8,%9},{%0,%1,%2,%3};"
        : "+f"(c[0]), "+f"(c[1]), "+f"(c[2]), "+f"(c[3])
        : "r"(a[0]), "r"(a[1]), "r"(a[2]), "r"(a[3]), "r"(b[0]), "r"(b[1]));
}

__global__ void __launch_bounds__(256) k_sgemm(
    const float* __restrict__ A, const float* __restrict__ Bm,
    const float* __restrict__ bias, const float* __restrict__ res,
    float* __restrict__ C, int M, const int* __restrict__ Mdev,
    int Npar, int K, const int* __restrict__ gidx,
    const float* __restrict__ gscale, int gelu_flag) {
    if (Mdev) M = *Mdev;
    int bm = blockIdx.y * 128, bn = blockIdx.x * 128;
    if (bm >= M) return;
    __shared__ __align__(16) float As[2][128][20];
    __shared__ __align__(16) float Bs[2][128][20];
    int tid = threadIdx.x;
    int warp = tid >> 5, lane = tid & 31;
    int wm = (warp & 3) * 32, wn = (warp >> 2) * 64;
    int qd = lane >> 2, rr = lane & 3;

    float c[2][8][4];
#pragma unroll
    for (int i = 0; i < 2; i++)
#pragma unroll
        for (int j = 0; j < 8; j++)
#pragma unroll
            for (int l = 0; l < 4; l++) c[i][j][l] = 0.f;

    int lrow = tid >> 1;
    int lk = (tid & 1) * 8;
    int am = bm + lrow;
    bool av = am < M;
    int asrc = 0;
    if (av) asrc = (gidx && !gscale) ? gidx[am] : am;
    const float* Ap = A + (size_t)asrc * K + lk;
    const float* Bp = Bm + (size_t)(bn + lrow) * K + lk;

    const float4 z4 = make_float4(0.f, 0.f, 0.f, 0.f);
    float4 fa0, fa1, fb0, fb1;

    // prologue: fetch+store tile 0
    fa0 = av ? *(const float4*)(Ap) : z4;
    fa1 = av ? *(const float4*)(Ap + 4) : z4;
    fb0 = *(const float4*)(Bp);
    fb1 = *(const float4*)(Bp + 4);
    *(float4*)&As[0][lrow][lk]     = cvt4_tf32(fa0);
    *(float4*)&As[0][lrow][lk + 4] = cvt4_tf32(fa1);
    *(float4*)&Bs[0][lrow][lk]     = cvt4_tf32(fb0);
    *(float4*)&Bs[0][lrow][lk + 4] = cvt4_tf32(fb1);
    __syncthreads();

    int ntiles = K >> 4;
    for (int kt = 0; kt < ntiles; kt++) {
        int buf = kt & 1;
        if (kt + 1 < ntiles) {
            const float* ap = Ap + (size_t)(kt + 1) * 16;
            const float* bp = Bp + (size_t)(kt + 1) * 16;
            fa0 = av ? *(const float4*)(ap) : z4;
            fa1 = av ? *(const float4*)(ap + 4) : z4;
            fb0 = *(const float4*)(bp);
            fb1 = *(const float4*)(bp + 4);
        }
#pragma unroll
        for (int ks = 0; ks < 2; ks++) {
            int k0 = ks * 8;
            uint32_t af[2][4];
#pragma unroll
            for (int mi = 0; mi < 2; mi++) {
                int rb = wm + mi * 16;
                af[mi][0] = __float_as_uint(As[buf][rb + qd][k0 + rr]);
                af[mi][1] = __float_as_uint(As[buf][rb + qd + 8][k0 + rr]);
                af[mi][2] = __float_as_uint(As[buf][rb + qd][k0 + rr + 4]);
                af[mi][3] = __float_as_uint(As[buf][rb + qd + 8][k0 + rr + 4]);
            }
            uint32_t bf[8][2];
#pragma unroll
            for (int ni = 0; ni < 8; ni++) {
                int cb = wn + ni * 8 + qd;
                bf[ni][0] = __float_as_uint(Bs[buf][cb][k0 + rr]);
                bf[ni][1] = __float_as_uint(Bs[buf][cb][k0 + rr + 4]);
            }
#pragma unroll
            for (int mi = 0; mi < 2; mi++)
#pragma unroll
                for (int ni = 0; ni < 8; ni++)
                    mma_tf32(c[mi][ni], af[mi], bf[ni]);
        }
        if (kt + 1 < ntiles) {
            int nb = (kt + 1) & 1;
            *(float4*)&As[nb][lrow][lk]     = cvt4_tf32(fa0);
            *(float4*)&As[nb][lrow][lk + 4] = cvt4_tf32(fa1);
            *(float4*)&Bs[nb][lrow][lk]     = cvt4_tf32(fb0);
            *(float4*)&Bs[nb][lrow][lk + 4] = cvt4_tf32(fb1);
        }
        __syncthreads();
    }

    // epilogue
#pragma unroll
    for (int mi = 0; mi < 2; mi++) {
#pragma unroll
        for (int hf = 0; hf < 2; hf++) {
            int m = bm + wm + mi * 16 + qd + hf * 8;
            if (m >= M) continue;
            int cr = gscale ? gidx[m] : m;
            float scv = gscale ? gscale[m] : 1.f;
            float* Crow = C + (size_t)cr * Npar;
            const float* Rrow = res ? res + (size_t)m * Npar : nullptr;
#pragma unroll
            for (int ni = 0; ni < 8; ni++) {
                int n = bn + wn + ni * 8 + 2 * rr;
                float v0 = c[mi][ni][hf * 2 + 0] + (bias ? bias[n] : 0.f);
                float v1 = c[mi][ni][hf * 2 + 1] + (bias ? bias[n + 1] : 0.f);
                if (gelu_flag) {
                    v0 = 0.5f * v0 * (1.f + erff(v0 * 0.70710678118654752f));
                    v1 = 0.5f * v1 * (1.f + erff(v1 * 0.70710678118654752f));
                }
                if (gscale) {
                    Crow[n] += v0 * scv;
                    Crow[n + 1] += v1 * scv;
                } else {
                    Crow[n] = v0 + (Rrow ? Rrow[n] : 0.f);
                    Crow[n + 1] = v1 + (Rrow ? Rrow[n + 1] : 0.f);
                }
            }
        }
    }
}

// ---------------- flash-style ALiBi attention (2 lanes per query) ----------
__global__ void __launch_bounds__(128) k_attn(const float* __restrict__ q,
                                              const float* __restrict__ k,
                                              const float* __restrict__ v,
                                              float* __restrict__ y) {
    int qt = blockIdx.x, h = blockIdx.y, b = blockIdx.z;
    int t = threadIdx.x;
    int qi = qt * 64 + (t >> 1);
    int half = (t & 1) * 32;
    __shared__ float Ks[64][64];
    __shared__ float Vs[64][64];
    float qr[32];
    const float* qp = q + ((size_t)(b * Nn + qi) * Dm + h * HD + half);
#pragma unroll
    for (int c = 0; c < 32; c += 4) {
        float4 f = *(const float4*)(qp + c);
        qr[c] = f.x; qr[c + 1] = f.y; qr[c + 2] = f.z; qr[c + 3] = f.w;
    }
    float o[32];
#pragma unroll
    for (int c = 0; c < 32; c++) o[c] = 0.f;
    float m = -1e30f, l = 0.f;
    float slope = exp2f(-0.5f * (float)(h + 1));
    for (int c0 = 0; c0 < Nn; c0 += 64) {
        for (int idx = t; idx < 64 * 64; idx += 128) {
            int row = idx >> 6, col = idx & 63;
            size_t base = ((size_t)(b * Nn + c0 + row) * Dm + h * HD);
            Ks[row][col] = k[base + col];
            Vs[row][col] = v[base + col];
        }
        __syncthreads();
        for (int j = 0; j < 64; j++) {
            float s0 = 0.f, s1 = 0.f, s2 = 0.f, s3 = 0.f;
            const float* kr = &Ks[j][half];
#pragma unroll
            for (int c = 0; c < 32; c += 4) {
                s0 += qr[c] * kr[c];
                s1 += qr[c + 1] * kr[c + 1];
                s2 += qr[c + 2] * kr[c + 2];
                s3 += qr[c + 3] * kr[c + 3];
            }
            float s = s0 + s1 + s2 + s3;
            s += __shfl_xor_sync(0xffffffffu, s, 1);
            s *= 0.125f;
            int dj = (c0 + j) - qi;
            if (dj > 0) s -= slope * (float)dj;
            float mn = fmaxf(m, s);
            float p = expf(s - mn);
            if (mn > m) {
                float corr = expf(m - mn);
                l *= corr;
#pragma unroll
                for (int c = 0; c < 32; c++) o[c] *= corr;
            }
            m = mn;
            l += p;
            const float* vr = &Vs[j][half];
#pragma unroll
            for (int c = 0; c < 32; c++) o[c] += p * vr[c];
        }
        __syncthreads();
    }
    float invl = 1.f / l;
    float* yp = y + ((size_t)(b * Nn + qi) * Dm + h * HD + half);
#pragma unroll
    for (int c = 0; c < 32; c++) yp[c] = o[c] * invl;
}

// ---------------- router: softmax gates, top-2, expert lists, aux sums -----
__global__ void k_router(const float* __restrict__ xf, const float* __restrict__ rw,
                         float* __restrict__ gatesum, int* __restrict__ icnt,
                         int* __restrict__ idxbuf, float* __restrict__ gwbuf) {
    int t = blockIdx.x;
    int tid = threadIdx.x;  // 128
    const float* xr = xf + (size_t)t * Dm;
    float a0 = 0.f, a1 = 0.f, a2 = 0.f, a3 = 0.f;
    for (int i = tid; i < Dm; i += 128) {
        float xv = xr[i];
        a0 += xv * rw[i];
        a1 += xv * rw[Dm + i];
        a2 += xv * rw[2 * Dm + i];
        a3 += xv * rw[3 * Dm + i];
    }
    __shared__ float red[4][128];
    red[0][tid] = a0; red[1][tid] = a1; red[2][tid] = a2; red[3][tid] = a3;
    __syncthreads();
    for (int st = 64; st > 0; st >>= 1) {
        if (tid < st) {
            red[0][tid] += red[0][tid + st];
            red[1][tid] += red[1][tid + st];
            red[2][tid] += red[2][tid + st];
            red[3][tid] += red[3][tid + st];
        }
        __syncthreads();
    }
    if (tid == 0) {
        float g[4];
        float mx = -1e30f;
        for (int e = 0; e < 4; e++) { g[e] = red[e][0]; mx = fmaxf(mx, g[e]); }
        float ssum = 0.f;
        for (int e = 0; e < 4; e++) { g[e] = expf(g[e] - mx); ssum += g[e]; }
        float sinv = 1.f / ssum;
        for (int e = 0; e < 4; e++) g[e] *= sinv;
        int i1 = 0;
        for (int e = 1; e < 4; e++) if (g[e] > g[i1]) i1 = e;
        int i2 = -1;
        for (int e = 0; e < 4; e++) if (e != i1 && (i2 < 0 || g[e] > g[i2])) i2 = e;
        float sum2 = g[i1] + g[i2];
        if (sum2 < 1e-9f) sum2 = 1e-9f;
        float w1 = g[i1] / sum2, w2 = g[i2] / sum2;
        for (int e = 0; e < 4; e++) atomicAdd(&gatesum[e], g[e]);
        int p1 = atomicAdd(&icnt[i1], 1);
        idxbuf[i1 * Tt_ + p1] = t; gwbuf[i1 * Tt_ + p1] = w1;
        int p2 = atomicAdd(&icnt[i2], 1);
        idxbuf[i2 * Tt_ + p2] = t; gwbuf[i2 * Tt_ + p2] = w2;
    }
}

__global__ void k_aux(const float* __restrict__ gatesum, const int* __restrict__ icnt,
                      float* __restrict__ out, int out_size) {
    const int MAIN = Bc * Nn * Dm;
    if (out_size <= MAIN) return;
    float aux = 0.f;
    for (int e = 0; e < 4; e++)
        aux += (gatesum[e] / (float)Tt_) * ((float)icnt[e] / (float)Tt_);
    out[out_size - 1] = 4.f * aux;
}

__global__ void k_zero(int* __restrict__ icnt, float* __restrict__ gatesum) {
    int i = threadIdx.x;
    if (i < 8) icnt[i] = 0;
    if (i < 4) gatesum[i] = 0.f;
}

// ---------------- trend conv: k=5, zero pad 2, + bias ----------------------
__global__ void k_trend(const float* __restrict__ trt, const float* __restrict__ tw,
                        const float* __restrict__ tb, float* __restrict__ tt) {
    int d = blockIdx.x, b = blockIdx.y;
    int tid = threadIdx.x;
    __shared__ float row[Nn];
    const float* rp = trt + ((size_t)b * Dm + d) * Nn;
    for (int i = tid; i < Nn; i += blockDim.x) row[i] = rp[i];
    __syncthreads();
    float w[5];
#pragma unroll
    for (int j = 0; j < 5; j++) w[j] = tw[d * 5 + j];
    float bb = tb[d];
    float* op = tt + ((size_t)b * Dm + d) * Nn;
    for (int n = tid; n < Nn; n += blockDim.x) {
        float acc = bb;
#pragma unroll
        for (int j = 0; j < 5; j++) {
            int t = n - 2 + j;
            if (t >= 0 && t < Nn) acc += w[j] * row[t];
        }
        op[n] = acc;
    }
}

// ---------------- launch ---------------------------------------------------
extern "C" void kernel_launch(void* const* d_in, const int* in_sizes, int n_in,
                              void* d_out, int out_size) {
    const float* x = (const float*)d_in[0];
    const float* qw = (const float*)d_in[1];  const float* qb = (const float*)d_in[2];
    const float* kw_ = (const float*)d_in[3]; const float* kb = (const float*)d_in[4];
    const float* vw = (const float*)d_in[5];  const float* vb = (const float*)d_in[6];
    const float* ow = (const float*)d_in[7];  const float* ob = (const float*)d_in[8];
    const float* n1g = (const float*)d_in[9]; const float* n1b = (const float*)d_in[10];
    const float* n2g = (const float*)d_in[11]; const float* n2b = (const float*)d_in[12];
    const float* alpha = (const float*)d_in[13];
    const float* dw7 = (const float*)d_in[14];
    const float* dw25 = (const float*)d_in[15];
    const float* dw49 = (const float*)d_in[16];
    const float* router_w = (const float*)d_in[17];
    const float* ew1 = (const float*)d_in[18]; const float* eb1 = (const float*)d_in[19];
    const float* ew2 = (const float*)d_in[20]; const float* eb2 = (const float*)d_in[21];
    const float* tw = (const float*)d_in[22];  const float* tb = (const float*)d_in[23];
    float* out = (float*)d_out;

    float* sc; cudaGetSymbolAddress((void**)&sc, g_scratch);
    int* isc; cudaGetSymbolAddress((void**)&isc, g_iscratch);
    const size_t MM = (size_t)8 * 1024 * 1024;
    float* xt = sc;            float* trt = sc + MM;
    float* S  = sc + 2 * MM;   float* Sn  = sc + 3 * MM;
    float* q  = sc + 4 * MM;   float* kk  = sc + 5 * MM;
    float* vv = sc + 6 * MM;   float* y   = sc + 7 * MM;
    float* xs = sc + 8 * MM;   float* xf  = sc + 9 * MM;
    float* hbuf = sc + 10 * MM;
    float* tt = sc + 12 * MM;
    float* gwbuf = sc + 13 * MM;
    float* gatesum = sc + 13 * MM + 4 * Tt_;
    int* icnt = isc;
    int* idxbuf = isc + 64;

    dim3 tb32(32, 8);
    k_zero<<<1, 32>>>(icnt, gatesum);
    k_transpose<<<dim3(32, 32, Bc), tb32>>>(x, xt);
    k_decomp<<<dim3(Dm, Bc), 128>>>(xt, dw7, dw25, dw49, alpha, trt);
    k_makeS<<<dim3(32, 32, Bc), tb32>>>(x, trt, S);
    k_ln<<<Tt_, 256>>>(S, n1g, n1b, Sn);
    dim3 gqkv(Dm / 128, Tt_ / 128);
    k_sgemm<<<gqkv, 256>>>(Sn, qw, qb, nullptr, q, Tt_, nullptr, Dm, Dm, nullptr, nullptr, 0);
    k_sgemm<<<gqkv, 256>>>(Sn, kw_, kb, nullptr, kk, Tt_, nullptr, Dm, Dm, nullptr, nullptr, 0);
    k_sgemm<<<gqkv, 256>>>(Sn, vw, vb, nullptr, vv, Tt_, nullptr, Dm, Dm, nullptr, nullptr, 0);
    k_attn<<<dim3(Nn / 64, Hh, Bc), 128>>>(q, kk, vv, y);
    k_sgemm<<<gqkv, 256>>>(y, ow, ob, S, xs, Tt_, nullptr, Dm, Dm, nullptr, nullptr, 0);
    k_ln<<<Tt_, 256>>>(xs, n2g, n2b, xf);
    k_router<<<Tt_, 128>>>(xf, router_w, gatesum, icnt, idxbuf, gwbuf);
    k_aux<<<1, 1>>>(gatesum, icnt, out, out_size);
    for (int e = 0; e < NE; e++) {
        k_sgemm<<<dim3(MH / 128, Tt_ / 128), 256>>>(
            xf, ew1 + (size_t)e * MH * Dm, eb1 + e * MH, nullptr, hbuf,
            0, &icnt[e], MH, Dm, idxbuf + e * Tt_, nullptr, 1);
        k_sgemm<<<dim3(Dm / 128, Tt_ / 128), 256>>>(
            hbuf, ew2 + (size_t)e * Dm * MH, eb2 + e * Dm, nullptr, xs,
            0, &icnt[e], Dm, MH, idxbuf + e * Tt_, gwbuf + e * Tt_, 0);
    }
    k_trend<<<dim3(Dm, Bc), 128>>>(trt, tw, tb, tt);
    k_final<<<dim3(32, 32, Bc), tb32>>>(xs, tt, out);
}